// round 9
// baseline (speedup 1.0000x reference)
#include <cuda_runtime.h>
#include <cuda_bf16.h>
#include <cstdint>

// ===========================================================================
// NNConv via mma.sync (HMMA) bf16 3-split GEMM — 512-thread edge kernel
// (16 warps, 4 warps/SMSP for latency hiding; warp tile 32m x 32n).
//   msg[e,o] = sum_{i,k} xj[e,i] H[e,k] w2[k, i*128+o]  + xj @ b2_reshaped
// A[e,(i,k)] = xj[e,i]*H[e,k] built on the fly in mma fragment registers,
// hi/lo bf16 split; B = w2^T pre-split/transposed/swizzled once.
// 3 MMAs per K16: Ahi*Bhi + Ahi*Blo + Alo*Bhi  (error ~2^-16 class).
// ===========================================================================

#define D   128
#define NE  16384
#define NN  10000
#define NS  258            // 256 (i,half) stages + 2 b2 stages
#define IMG 16384          // bytes per B split image (128 o x 64 k bf16, SW128)

typedef unsigned int       u32;
typedef unsigned long long u64;

// ---------------- device scratch (no allocations allowed) ----------------
__device__ float g_seg[(size_t)NN * D];
__device__ float g_cnt[NN];
__device__ int   g_is64;
__device__ unsigned char g_Bhi[(size_t)NS * IMG];
__device__ unsigned char g_Blo[(size_t)NS * IMG];

// ---------------- PTX helpers ----------------
__device__ __forceinline__ u32 smem_u32(const void* p) {
    u32 a;
    asm("{ .reg .u64 t; cvta.to.shared.u64 t, %1; cvt.u32.u64 %0, t; }"
        : "=r"(a) : "l"(p));
    return a;
}
__device__ __forceinline__ void cpa16(u32 dst, const void* src) {
    asm volatile("cp.async.cg.shared.global [%0], [%1], 16;"
                 :: "r"(dst), "l"(src));
}
__device__ __forceinline__ void cpa_commit() {
    asm volatile("cp.async.commit_group;" ::: "memory");
}
__device__ __forceinline__ void cpa_wait2() {
    asm volatile("cp.async.wait_group 2;" ::: "memory");
}
__device__ __forceinline__ void ldmx4(u32& r0, u32& r1, u32& r2, u32& r3, u32 addr) {
    asm volatile("ldmatrix.sync.aligned.m8n8.x4.shared.b16 {%0,%1,%2,%3}, [%4];"
                 : "=r"(r0), "=r"(r1), "=r"(r2), "=r"(r3) : "r"(addr));
}
__device__ __forceinline__ void hmma(float* d, const u32* a, const u32* b) {
    asm volatile(
        "mma.sync.aligned.m16n8k16.row.col.f32.bf16.bf16.f32 "
        "{%0,%1,%2,%3}, {%4,%5,%6,%7}, {%8,%9}, {%0,%1,%2,%3};"
        : "+f"(d[0]), "+f"(d[1]), "+f"(d[2]), "+f"(d[3])
        : "r"(a[0]), "r"(a[1]), "r"(a[2]), "r"(a[3]), "r"(b[0]), "r"(b[1]));
}

#define SWZ(off) ((off) ^ (((off) >> 3) & 0x70))

// bf16 hi/lo split of a (k, k+1) pair into packed bf16x2 (low half = k)
__device__ __forceinline__ void split2(float p0, float p1, u32& h, u32& l) {
    u32 hp;
    asm("cvt.rn.bf16x2.f32 %0, %1, %2;" : "=r"(hp) : "f"(p1), "f"(p0));
    float f0 = __uint_as_float(hp << 16);
    float f1 = __uint_as_float(hp & 0xffff0000u);
    u32 lp;
    float r0 = p0 - f0, r1 = p1 - f1;
    asm("cvt.rn.bf16x2.f32 %0, %1, %2;" : "=r"(lp) : "f"(r1), "f"(r0));
    h = hp; l = lp;
}

// ---------------- edge-index width detection ----------------
__global__ void detect_kernel(const int* __restrict__ ei) {
    if (threadIdx.x < 32) {
        int v = 0;
        for (int j = threadIdx.x; j < 512; j += 32) v |= ei[2 * j + 1];
        #pragma unroll
        for (int o = 16; o; o >>= 1) v |= __shfl_xor_sync(0xffffffffu, v, o);
        if (threadIdx.x == 0) g_is64 = (v == 0) ? 1 : 0;
    }
}
__device__ __forceinline__ int load_edge(const int* __restrict__ ei, int which,
                                         int e, int is64) {
    return is64 ? ei[2 * (which * NE + e)] : ei[which * NE + e];
}

__global__ void zero_kernel() {
    int i = blockIdx.x * blockDim.x + threadIdx.x;
    if (i < NN * D) g_seg[i] = 0.f;
    if (i < NN)     g_cnt[i] = 0.f;
}
__global__ void cnt_kernel(const int* __restrict__ ei) {
    int e = blockIdx.x * blockDim.x + threadIdx.x;
    if (e < NE) atomicAdd(&g_cnt[load_edge(ei, 1, e, g_is64)], 1.f);
}

// ---------------- prep: split/transpose/swizzle w2 (and b2) ----------------
__global__ __launch_bounds__(128) void prep_kernel(const float* __restrict__ w2,
                                                   const float* __restrict__ b2) {
    __shared__ unsigned char img[2][IMG];
    const int s = blockIdx.x;     // 0..257
    const int o = threadIdx.x;    // 0..127
    for (int kk = 0; kk < 64; kk++) {
        float v;
        if (s < 256) {
            int i = s >> 1, h = s & 1;
            v = w2[(size_t)(64 * h + kk) * (D * D) + (size_t)i * D + o];
        } else {
            int j = s - 256;
            v = b2[(64 * j + kk) * D + o];
        }
        __nv_bfloat16 hb = __float2bfloat16(v);
        float rem = v - __bfloat162float(hb);
        __nv_bfloat16 lb = __float2bfloat16(rem);
        u32 off = SWZ((u32)(o * 128 + kk * 2));
        *(unsigned short*)&img[0][off] = __bfloat16_as_ushort(hb);
        *(unsigned short*)&img[1][off] = __bfloat16_as_ushort(lb);
    }
    __syncthreads();
    const float4* s0 = (const float4*)img[0];
    const float4* s1 = (const float4*)img[1];
    float4* d0 = (float4*)(g_Bhi + (size_t)s * IMG);
    float4* d1 = (float4*)(g_Blo + (size_t)s * IMG);
    #pragma unroll
    for (int r = 0; r < 8; r++) {
        d0[o + r * 128] = s0[o + r * 128];
        d1[o + r * 128] = s1[o + r * 128];
    }
}

// ---------------- main edge kernel (512 threads) ----------------
// smem: [0,96K) B bufs (3 x {hi16K, lo16K}); [96K,160K) XJT f32 [i][e];
//       [160K, +66560) HT2 float2 [k/2][e] stride 130
#define SM_B    0
#define SM_XJT  (96 * 1024)
#define SM_HT   (160 * 1024)
#define HSTR    130
#define EDGE_SMEM_BYTES (160 * 1024 + 64 * HSTR * 8)

__global__ __launch_bounds__(512, 1) void edge_kernel(
    const float* __restrict__ x,  const int* __restrict__ ei,
    const float* __restrict__ ea, const float* __restrict__ w1,
    const float* __restrict__ b1)
{
    extern __shared__ unsigned char smraw[];
    float*  XJT = (float*) (smraw + SM_XJT);
    float2* HT2 = (float2*)(smraw + SM_HT);
    float*  EAT = (float*) (smraw + SM_B);   // phase-0 alias (64KB of B region)
    float*  W1s = XJT;                        // phase-0 alias

    const int tid  = threadIdx.x;
    const int lane = tid & 31;
    const int wid  = tid >> 5;     // 0..15
    const int wm   = wid >> 2;     // C row block (0..3) * 32
    const int wn   = wid & 3;      // C col block (0..3) * 32
    const int l4   = lane & 3;
    const int l28  = lane >> 2;
    const int e0   = blockIdx.x * 128;
    const int is64 = g_is64;

    // ---- phase 0: stage edge_attr^T and w1 (512 thr: 4 per row) ----
    {
        const int e  = tid >> 2;
        const int c0 = (tid & 3) * 32;
        const float* row = ea + (size_t)(e0 + e) * D + c0;
        #pragma unroll
        for (int j = 0; j < 32; j += 4) {
            float4 v = *(const float4*)(row + j);
            EAT[(c0 + j + 0) * 128 + e] = v.x;
            EAT[(c0 + j + 1) * 128 + e] = v.y;
            EAT[(c0 + j + 2) * 128 + e] = v.z;
            EAT[(c0 + j + 3) * 128 + e] = v.w;
        }
        const float* wr = w1 + (size_t)(tid >> 2) * D + c0;
        float* wd = W1s + (tid >> 2) * 128 + c0;
        #pragma unroll
        for (int j = 0; j < 32; j += 4)
            *(float4*)(wd + j) = *(const float4*)(wr + j);
    }
    __syncthreads();

    // ---- phase 1: H = relu(EA @ w1 + b1) -> HT2[k/2][e] (512 thr: 4x8 tile) ----
    {
        const int tx = tid & 15, ty = tid >> 4;   // ty 0..31 -> 4 rows each
        float hacc[4][8];
        #pragma unroll
        for (int r = 0; r < 4; r++)
            #pragma unroll
            for (int c = 0; c < 8; c++) hacc[r][c] = 0.f;
        for (int c = 0; c < 128; c++) {
            float4 aL = *(const float4*)&EAT[c * 128 + ty * 4];
            float4 bL = *(const float4*)&W1s[c * 128 + tx * 8];
            float4 bH = *(const float4*)&W1s[c * 128 + tx * 8 + 4];
            float a[4] = {aL.x, aL.y, aL.z, aL.w};
            float b[8] = {bL.x, bL.y, bL.z, bL.w, bH.x, bH.y, bH.z, bH.w};
            #pragma unroll
            for (int r = 0; r < 4; r++)
                #pragma unroll
                for (int c2 = 0; c2 < 8; c2++)
                    hacc[r][c2] = fmaf(a[r], b[c2], hacc[r][c2]);
        }
        __syncthreads();   // EAT/W1s reads done before regions are reused
        #pragma unroll
        for (int j = 0; j < 4; j++) {      // k pair (tx*8+2j, tx*8+2j+1)
            const float bb0 = b1[tx * 8 + 2 * j];
            const float bb1 = b1[tx * 8 + 2 * j + 1];
            const int q = tx * 4 + j;
            #pragma unroll
            for (int r = 0; r < 4; r++) {
                float2 v;
                v.x = fmaxf(hacc[r][2 * j]     + bb0, 0.f);
                v.y = fmaxf(hacc[r][2 * j + 1] + bb1, 0.f);
                HT2[q * HSTR + ty * 4 + r] = v;
            }
        }
    }

    // ---- gather x[src]^T -> XJT[i][e] (overwrites W1s region) ----
    {
        const int e  = tid >> 2;
        const int i0 = (tid & 3) * 32;
        const int s  = load_edge(ei, 0, e0 + e, is64);
        const float* xr = x + (size_t)s * D + i0;
        #pragma unroll
        for (int j = 0; j < 32; j += 4) {
            float4 v = *(const float4*)(xr + j);
            XJT[(i0 + j + 0) * 128 + e] = v.x;
            XJT[(i0 + j + 1) * 128 + e] = v.y;
            XJT[(i0 + j + 2) * 128 + e] = v.z;
            XJT[(i0 + j + 3) * 128 + e] = v.w;
        }
    }
    __syncthreads();     // XJT/HT2 ready, EAT region free for B buffers

    // ---- prologue: prefetch B stages 0,1,2 (4 x 16B per thread) ----
    #pragma unroll
    for (int ps = 0; ps < 3; ps++) {
        u32 db = smem_u32(smraw + SM_B + ps * 32768);
        const unsigned char* sh = g_Bhi + (size_t)ps * IMG;
        const unsigned char* sl = g_Blo + (size_t)ps * IMG;
        const int o1 = tid * 16, o2 = tid * 16 + 8192;
        cpa16(db + o1,          sh + o1);
        cpa16(db + o2,          sh + o2);
        cpa16(db + 16384 + o1,  sl + o1);
        cpa16(db + 16384 + o2,  sl + o2);
        cpa_commit();
    }

    // ---- accumulators: 32m x 32n per warp ----
    float dacc[2][4][4];
    #pragma unroll
    for (int mh = 0; mh < 2; mh++)
        #pragma unroll
        for (int j = 0; j < 4; j++)
            #pragma unroll
            for (int q = 0; q < 4; q++) dacc[mh][j][q] = 0.f;

    const int r0b = wm * 32 + l28;       // base row (mh adds 16)

    // ---- main loop over 258 stages ----
    for (int s = 0; s < NS; s++) {
        cpa_wait2();          // stage s resident (this thread's groups)
        __syncthreads();      // all threads' stage-s data visible

        const u32 bb = smem_u32(smraw + SM_B + (s % 3) * 32768);
        const int i  = s >> 1;
        const int h  = s & 1;
        const int j2 = s - 256;

        float xv0_0 = 0.f, xv1_0 = 0.f, xv0_1 = 0.f, xv1_1 = 0.f;
        if (s < 256) {
            xv0_0 = XJT[i * 128 + r0b];
            xv1_0 = XJT[i * 128 + r0b + 8];
            xv0_1 = XJT[i * 128 + r0b + 16];
            xv1_1 = XJT[i * 128 + r0b + 24];
        }

        #pragma unroll
        for (int c = 0; c < 4; c++) {     // K16 chunks
            // --- build A fragments in registers ---
            u32 Ahi[2][4], Alo[2][4];
            if (s < 256) {
                const int qb = h * 32 + c * 8 + l4;
                #pragma unroll
                for (int mh = 0; mh < 2; mh++) {
                    const int rr0 = r0b + mh * 16;
                    const float xa = mh ? xv0_1 : xv0_0;
                    const float xb = mh ? xv1_1 : xv1_0;
                    float2 h00 = HT2[qb * HSTR + rr0];
                    float2 h01 = HT2[qb * HSTR + rr0 + 8];
                    float2 h10 = HT2[(qb + 4) * HSTR + rr0];
                    float2 h11 = HT2[(qb + 4) * HSTR + rr0 + 8];
                    split2(xa * h00.x, xa * h00.y, Ahi[mh][0], Alo[mh][0]);
                    split2(xb * h01.x, xb * h01.y, Ahi[mh][1], Alo[mh][1]);
                    split2(xa * h10.x, xa * h10.y, Ahi[mh][2], Alo[mh][2]);
                    split2(xb * h11.x, xb * h11.y, Ahi[mh][3], Alo[mh][3]);
                }
            } else {
                const int kb = j2 * 64 + c * 16 + l4 * 2;
                #pragma unroll
                for (int mh = 0; mh < 2; mh++) {
                    const int rr0 = r0b + mh * 16;
                    split2(XJT[(kb + 0) * 128 + rr0],     XJT[(kb + 1) * 128 + rr0],
                           Ahi[mh][0], Alo[mh][0]);
                    split2(XJT[(kb + 0) * 128 + rr0 + 8], XJT[(kb + 1) * 128 + rr0 + 8],
                           Ahi[mh][1], Alo[mh][1]);
                    split2(XJT[(kb + 8) * 128 + rr0],     XJT[(kb + 9) * 128 + rr0],
                           Ahi[mh][2], Alo[mh][2]);
                    split2(XJT[(kb + 8) * 128 + rr0 + 8], XJT[(kb + 9) * 128 + rr0 + 8],
                           Ahi[mh][3], Alo[mh][3]);
                }
            }

            // --- load B fragments (ldmatrix.x4, pre-swizzled [n][k] images) ---
            // warp covers n in [wn*32, wn*32+32): 4 n8-blocks, 2 ldmx4 per image
            u32 Bhi[4][2], Blo[4][2];
            {
                const int grp = lane >> 3;
                const int rr  = lane & 7;
                #pragma unroll
                for (int jj = 0; jj < 2; jj++) {   // n8-block pairs (2jj, 2jj+1)
                    const int n = wn * 32 + (2 * jj + (grp >> 1)) * 8 + rr;
                    const u32 off = (u32)(n * 128 + c * 32 + (grp & 1) * 16);
                    const u32 ah = bb + SWZ(off);
                    ldmx4(Bhi[2*jj][0], Bhi[2*jj][1], Bhi[2*jj+1][0], Bhi[2*jj+1][1], ah);
                    ldmx4(Blo[2*jj][0], Blo[2*jj][1], Blo[2*jj+1][0], Blo[2*jj+1][1],
                          ah + 16384);
                }
            }

            // --- 24 HMMA: 3-split x 2m x 4n ---
            #pragma unroll
            for (int j = 0; j < 4; j++)
                #pragma unroll
                for (int mh = 0; mh < 2; mh++) {
                    hmma(dacc[mh][j], Ahi[mh], Bhi[j]);
                    hmma(dacc[mh][j], Ahi[mh], Blo[j]);
                    hmma(dacc[mh][j], Alo[mh], Bhi[j]);
                }
        }
        __syncthreads();      // all reads of buf s%3 done before refill below

        // issue stage s+3 into buf (s+3)%3 == s%3
        const int sp = s + 3;
        if (sp < NS) {
            u32 db = smem_u32(smraw + SM_B + (sp % 3) * 32768);
            const unsigned char* sh = g_Bhi + (size_t)sp * IMG;
            const unsigned char* sl = g_Blo + (size_t)sp * IMG;
            const int o1 = tid * 16, o2 = tid * 16 + 8192;
            cpa16(db + o1,          sh + o1);
            cpa16(db + o2,          sh + o2);
            cpa16(db + 16384 + o1,  sl + o1);
            cpa16(db + 16384 + o2,  sl + o2);
        }
        cpa_commit();
    }

    // ---- epilogue: scatter-add fragments into g_seg ----
    #pragma unroll
    for (int mh = 0; mh < 2; mh++) {
        const int r0 = r0b + mh * 16;
        const int d0i = load_edge(ei, 1, e0 + r0,     is64);
        const int d1i = load_edge(ei, 1, e0 + r0 + 8, is64);
        float* g0 = g_seg + (size_t)d0i * D;
        float* g1 = g_seg + (size_t)d1i * D;
        #pragma unroll
        for (int j = 0; j < 4; j++) {
            const int nc = wn * 32 + j * 8 + l4 * 2;
            atomicAdd(&g0[nc],     dacc[mh][j][0]);
            atomicAdd(&g0[nc + 1], dacc[mh][j][1]);
            atomicAdd(&g1[nc],     dacc[mh][j][2]);
            atomicAdd(&g1[nc + 1], dacc[mh][j][3]);
        }
    }
}

// ---------------- node kernel: out = x + gelu(aggr + x@root + bias) ----------------
#define NSTR 132
#define NODE_SMEM_BYTES ((128 * NSTR + 128 * 128) * 4)

__global__ __launch_bounds__(256, 1) void node_kernel(
    const float* __restrict__ x, const float* __restrict__ root,
    const float* __restrict__ bias, float* __restrict__ out)
{
    extern __shared__ float sm[];
    float* XT = sm;
    float* Rs = sm + 128 * NSTR;

    const int tid = threadIdx.x;
    const int tx  = tid & 15;
    const int ty  = tid >> 4;
    const int n0  = blockIdx.x * 128;

    {
        const int e  = tid >> 1;
        const int c0 = (tid & 1) * 64;
        const int n  = n0 + e;
        if (n < NN) {
            const float* row = x + (size_t)n * D + c0;
            #pragma unroll
            for (int j = 0; j < 64; j += 4) {
                float4 v = *(const float4*)(row + j);
                XT[(c0 + j + 0) * NSTR + e] = v.x;
                XT[(c0 + j + 1) * NSTR + e] = v.y;
                XT[(c0 + j + 2) * NSTR + e] = v.z;
                XT[(c0 + j + 3) * NSTR + e] = v.w;
            }
        } else {
            #pragma unroll
            for (int j = 0; j < 64; j++)
                XT[(c0 + j) * NSTR + e] = 0.f;
        }
        const float* rr = root + (size_t)(tid >> 1) * D + c0;
        float* rd = Rs + (tid >> 1) * 128 + c0;
        #pragma unroll
        for (int j = 0; j < 64; j += 4)
            *(float4*)(rd + j) = *(const float4*)(rr + j);
    }
    __syncthreads();

    float acc[8][8];
    #pragma unroll
    for (int r = 0; r < 8; r++)
        #pragma unroll
        for (int c = 0; c < 8; c++) acc[r][c] = 0.f;

    for (int c = 0; c < 128; c++) {
        float4 aL = *(const float4*)&XT[c * NSTR + ty * 8];
        float4 aH = *(const float4*)&XT[c * NSTR + ty * 8 + 4];
        float4 bL = *(const float4*)&Rs[c * 128 + tx * 8];
        float4 bH = *(const float4*)&Rs[c * 128 + tx * 8 + 4];
        float a[8] = {aL.x, aL.y, aL.z, aL.w, aH.x, aH.y, aH.z, aH.w};
        float b[8] = {bL.x, bL.y, bL.z, bL.w, bH.x, bH.y, bH.z, bH.w};
        #pragma unroll
        for (int r = 0; r < 8; r++)
            #pragma unroll
            for (int c2 = 0; c2 < 8; c2++)
                acc[r][c2] = fmaf(a[r], b[c2], acc[r][c2]);
    }

    #pragma unroll
    for (int r = 0; r < 8; r++) {
        const int n = n0 + ty * 8 + r;
        if (n >= NN) continue;
        const float invc = 1.f / fmaxf(g_cnt[n], 1.f);
        #pragma unroll
        for (int c = 0; c < 8; c++) {
            const int o = tx * 8 + c;
            float cv = acc[r][c] + bias[o] + g_seg[(size_t)n * D + o] * invc;
            float xv = XT[o * NSTR + ty * 8 + r];
            out[(size_t)n * D + o] = xv + cv * normcdff(cv);
        }
    }
}

// ---------------- launch ----------------
extern "C" void kernel_launch(void* const* d_in, const int* in_sizes, int n_in,
                              void* d_out, int out_size)
{
    const float* x    = (const float*)d_in[0];
    const int*   ei   = (const int*)  d_in[1];
    const float* ea   = (const float*)d_in[2];
    const float* w1   = (const float*)d_in[3];
    const float* b1   = (const float*)d_in[4];
    const float* w2   = (const float*)d_in[5];
    const float* b2   = (const float*)d_in[6];
    const float* root = (const float*)d_in[7];
    const float* bias = (const float*)d_in[8];
    float* out = (float*)d_out;

    cudaFuncSetAttribute(edge_kernel, cudaFuncAttributeMaxDynamicSharedMemorySize,
                         EDGE_SMEM_BYTES);
    cudaFuncSetAttribute(node_kernel, cudaFuncAttributeMaxDynamicSharedMemorySize,
                         NODE_SMEM_BYTES);

    detect_kernel<<<1, 32>>>(ei);
    zero_kernel<<<(NN * D + 255) / 256, 256>>>();
    cnt_kernel<<<(NE + 255) / 256, 256>>>(ei);
    prep_kernel<<<NS, 128>>>(w2, b2);
    edge_kernel<<<NE / 128, 512, EDGE_SMEM_BYTES>>>(x, ei, ea, w1, b1);
    node_kernel<<<(NN + 127) / 128, 256, NODE_SMEM_BYTES>>>(x, root, bias, out);
}

// round 10
// speedup vs baseline: 1.2751x; 1.2751x over previous
#include <cuda_runtime.h>
#include <cuda_bf16.h>
#include <cstdint>

// ===========================================================================
// NNConv via mma.sync (HMMA) bf16 3-split GEMM — 256 threads, m16n128 warp
// tile: each warp owns 16 UNIQUE rows -> zero duplicated A-generation.
//   msg[e,o] = sum_{i,k} xj[e,i] H[e,k] w2[k, i*128+o]  + xj @ b2_reshaped
// A[e,(i,k)] = xj[e,i]*H[e,k] built on the fly in mma fragment registers,
// hi/lo bf16 split; B = w2^T pre-split/transposed/swizzled once.
// 3 MMAs per K16: Ahi*Bhi + Ahi*Blo + Alo*Bhi.
// ===========================================================================

#define D   128
#define NE  16384
#define NN  10000
#define NS  258            // 256 (i,half) stages + 2 b2 stages
#define IMG 16384          // bytes per B split image (128 o x 64 k bf16, SW128)

typedef unsigned int       u32;
typedef unsigned long long u64;

// ---------------- device scratch (no allocations allowed) ----------------
__device__ float g_seg[(size_t)NN * D];
__device__ float g_cnt[NN];
__device__ int   g_is64;
__device__ unsigned char g_Bhi[(size_t)NS * IMG];
__device__ unsigned char g_Blo[(size_t)NS * IMG];

// ---------------- PTX helpers ----------------
__device__ __forceinline__ u32 smem_u32(const void* p) {
    u32 a;
    asm("{ .reg .u64 t; cvta.to.shared.u64 t, %1; cvt.u32.u64 %0, t; }"
        : "=r"(a) : "l"(p));
    return a;
}
__device__ __forceinline__ void cpa16(u32 dst, const void* src) {
    asm volatile("cp.async.cg.shared.global [%0], [%1], 16;"
                 :: "r"(dst), "l"(src));
}
__device__ __forceinline__ void cpa_commit() {
    asm volatile("cp.async.commit_group;" ::: "memory");
}
__device__ __forceinline__ void cpa_wait2() {
    asm volatile("cp.async.wait_group 2;" ::: "memory");
}
__device__ __forceinline__ void ldmx4(u32& r0, u32& r1, u32& r2, u32& r3, u32 addr) {
    asm volatile("ldmatrix.sync.aligned.m8n8.x4.shared.b16 {%0,%1,%2,%3}, [%4];"
                 : "=r"(r0), "=r"(r1), "=r"(r2), "=r"(r3) : "r"(addr));
}
__device__ __forceinline__ void hmma(float* d, const u32* a, const u32* b) {
    asm volatile(
        "mma.sync.aligned.m16n8k16.row.col.f32.bf16.bf16.f32 "
        "{%0,%1,%2,%3}, {%4,%5,%6,%7}, {%8,%9}, {%0,%1,%2,%3};"
        : "+f"(d[0]), "+f"(d[1]), "+f"(d[2]), "+f"(d[3])
        : "r"(a[0]), "r"(a[1]), "r"(a[2]), "r"(a[3]), "r"(b[0]), "r"(b[1]));
}

#define SWZ(off) ((off) ^ (((off) >> 3) & 0x70))

// bf16 hi/lo split of a (k, k+1) pair into packed bf16x2 (low half = k)
__device__ __forceinline__ void split2(float p0, float p1, u32& h, u32& l) {
    u32 hp;
    asm("cvt.rn.bf16x2.f32 %0, %1, %2;" : "=r"(hp) : "f"(p1), "f"(p0));
    float f0 = __uint_as_float(hp << 16);
    float f1 = __uint_as_float(hp & 0xffff0000u);
    u32 lp;
    float r0 = p0 - f0, r1 = p1 - f1;
    asm("cvt.rn.bf16x2.f32 %0, %1, %2;" : "=r"(lp) : "f"(r1), "f"(r0));
    h = hp; l = lp;
}

// ---------------- edge-index width detection ----------------
__global__ void detect_kernel(const int* __restrict__ ei) {
    if (threadIdx.x < 32) {
        int v = 0;
        for (int j = threadIdx.x; j < 512; j += 32) v |= ei[2 * j + 1];
        #pragma unroll
        for (int o = 16; o; o >>= 1) v |= __shfl_xor_sync(0xffffffffu, v, o);
        if (threadIdx.x == 0) g_is64 = (v == 0) ? 1 : 0;
    }
}
__device__ __forceinline__ int load_edge(const int* __restrict__ ei, int which,
                                         int e, int is64) {
    return is64 ? ei[2 * (which * NE + e)] : ei[which * NE + e];
}

__global__ void zero_kernel() {
    int i = blockIdx.x * blockDim.x + threadIdx.x;
    if (i < NN * D) g_seg[i] = 0.f;
    if (i < NN)     g_cnt[i] = 0.f;
}
__global__ void cnt_kernel(const int* __restrict__ ei) {
    int e = blockIdx.x * blockDim.x + threadIdx.x;
    if (e < NE) atomicAdd(&g_cnt[load_edge(ei, 1, e, g_is64)], 1.f);
}

// ---------------- prep: split/transpose/swizzle w2 (and b2) ----------------
__global__ __launch_bounds__(128) void prep_kernel(const float* __restrict__ w2,
                                                   const float* __restrict__ b2) {
    __shared__ unsigned char img[2][IMG];
    const int s = blockIdx.x;     // 0..257
    const int o = threadIdx.x;    // 0..127
    for (int kk = 0; kk < 64; kk++) {
        float v;
        if (s < 256) {
            int i = s >> 1, h = s & 1;
            v = w2[(size_t)(64 * h + kk) * (D * D) + (size_t)i * D + o];
        } else {
            int j = s - 256;
            v = b2[(64 * j + kk) * D + o];
        }
        __nv_bfloat16 hb = __float2bfloat16(v);
        float rem = v - __bfloat162float(hb);
        __nv_bfloat16 lb = __float2bfloat16(rem);
        u32 off = SWZ((u32)(o * 128 + kk * 2));
        *(unsigned short*)&img[0][off] = __bfloat16_as_ushort(hb);
        *(unsigned short*)&img[1][off] = __bfloat16_as_ushort(lb);
    }
    __syncthreads();
    const float4* s0 = (const float4*)img[0];
    const float4* s1 = (const float4*)img[1];
    float4* d0 = (float4*)(g_Bhi + (size_t)s * IMG);
    float4* d1 = (float4*)(g_Blo + (size_t)s * IMG);
    #pragma unroll
    for (int r = 0; r < 8; r++) {
        d0[o + r * 128] = s0[o + r * 128];
        d1[o + r * 128] = s1[o + r * 128];
    }
}

// ---------------- main edge kernel (256 threads, m16n128 warp tiles) ------
// smem: [0,96K) B bufs (3 x {hi16K, lo16K}); [96K,160K) XJT f32 [i][e];
//       [160K, +66560) HT2 float2 [k/2][e] stride 130
#define SM_B    0
#define SM_XJT  (96 * 1024)
#define SM_HT   (160 * 1024)
#define HSTR    130
#define EDGE_SMEM_BYTES (160 * 1024 + 64 * HSTR * 8)

__global__ __launch_bounds__(256, 1) void edge_kernel(
    const float* __restrict__ x,  const int* __restrict__ ei,
    const float* __restrict__ ea, const float* __restrict__ w1,
    const float* __restrict__ b1)
{
    extern __shared__ unsigned char smraw[];
    float*  XJT = (float*) (smraw + SM_XJT);
    float2* HT2 = (float2*)(smraw + SM_HT);
    float*  EAT = (float*) (smraw + SM_B);   // phase-0 alias (64KB of B region)
    float*  W1s = XJT;                        // phase-0 alias

    const int tid  = threadIdx.x;
    const int lane = tid & 31;
    const int wid  = tid >> 5;     // 0..7: row block (wid*16)
    const int l4   = lane & 3;
    const int l28  = lane >> 2;
    const int e0   = blockIdx.x * 128;
    const int is64 = g_is64;

    // ---- phase 0: stage edge_attr^T and w1 ----
    {
        const int e  = tid >> 1;
        const int c0 = (tid & 1) * 64;
        const float* row = ea + (size_t)(e0 + e) * D + c0;
        #pragma unroll
        for (int j = 0; j < 64; j += 4) {
            float4 v = *(const float4*)(row + j);
            EAT[(c0 + j + 0) * 128 + e] = v.x;
            EAT[(c0 + j + 1) * 128 + e] = v.y;
            EAT[(c0 + j + 2) * 128 + e] = v.z;
            EAT[(c0 + j + 3) * 128 + e] = v.w;
        }
        const float* wr = w1 + (size_t)(tid >> 1) * D + c0;
        float* wd = W1s + (tid >> 1) * 128 + c0;
        #pragma unroll
        for (int j = 0; j < 64; j += 4)
            *(float4*)(wd + j) = *(const float4*)(wr + j);
    }
    __syncthreads();

    // ---- phase 1: H = relu(EA @ w1 + b1) -> HT2[k/2][e] (pairs, stride 130) ----
    {
        const int tx = tid & 15, ty = tid >> 4;
        float hacc[8][8];
        #pragma unroll
        for (int r = 0; r < 8; r++)
            #pragma unroll
            for (int c = 0; c < 8; c++) hacc[r][c] = 0.f;
        for (int c = 0; c < 128; c++) {
            float4 aL = *(const float4*)&EAT[c * 128 + ty * 8];
            float4 aH = *(const float4*)&EAT[c * 128 + ty * 8 + 4];
            float4 bL = *(const float4*)&W1s[c * 128 + tx * 8];
            float4 bH = *(const float4*)&W1s[c * 128 + tx * 8 + 4];
            float a[8] = {aL.x, aL.y, aL.z, aL.w, aH.x, aH.y, aH.z, aH.w};
            float b[8] = {bL.x, bL.y, bL.z, bL.w, bH.x, bH.y, bH.z, bH.w};
            #pragma unroll
            for (int r = 0; r < 8; r++)
                #pragma unroll
                for (int c2 = 0; c2 < 8; c2++)
                    hacc[r][c2] = fmaf(a[r], b[c2], hacc[r][c2]);
        }
        __syncthreads();   // EAT/W1s reads done before regions are reused
        #pragma unroll
        for (int j = 0; j < 4; j++) {      // k pair (tx*8+2j, tx*8+2j+1)
            const float bb0 = b1[tx * 8 + 2 * j];
            const float bb1 = b1[tx * 8 + 2 * j + 1];
            const int q = tx * 4 + j;
            #pragma unroll
            for (int r = 0; r < 8; r++) {
                float2 v;
                v.x = fmaxf(hacc[r][2 * j]     + bb0, 0.f);
                v.y = fmaxf(hacc[r][2 * j + 1] + bb1, 0.f);
                HT2[q * HSTR + ty * 8 + r] = v;
            }
        }
    }

    // ---- gather x[src]^T -> XJT[i][e] (overwrites W1s region) ----
    {
        const int e  = tid >> 1;
        const int i0 = (tid & 1) * 64;
        const int s  = load_edge(ei, 0, e0 + e, is64);
        const float* xr = x + (size_t)s * D + i0;
        #pragma unroll
        for (int j = 0; j < 64; j += 4) {
            float4 v = *(const float4*)(xr + j);
            XJT[(i0 + j + 0) * 128 + e] = v.x;
            XJT[(i0 + j + 1) * 128 + e] = v.y;
            XJT[(i0 + j + 2) * 128 + e] = v.z;
            XJT[(i0 + j + 3) * 128 + e] = v.w;
        }
    }
    __syncthreads();     // XJT/HT2 ready, EAT region free for B buffers

    // ---- prologue: prefetch B stages 0,1,2 ----
    #pragma unroll
    for (int ps = 0; ps < 3; ps++) {
        u32 db = smem_u32(smraw + SM_B + ps * 32768) + tid * 16;
        const unsigned char* sh = g_Bhi + (size_t)ps * IMG + tid * 16;
        const unsigned char* sl = g_Blo + (size_t)ps * IMG + tid * 16;
        #pragma unroll
        for (int r = 0; r < 4; r++) {
            cpa16(db + r * 4096,         sh + r * 4096);
            cpa16(db + 16384 + r * 4096, sl + r * 4096);
        }
        cpa_commit();
    }

    // ---- accumulators: 16m x 128n per warp ----
    float dacc[16][4];
    #pragma unroll
    for (int j = 0; j < 16; j++)
        #pragma unroll
        for (int q = 0; q < 4; q++) dacc[j][q] = 0.f;

    const int r0b = wid * 16 + l28;      // rows r0b and r0b+8

    // ---- main loop over 258 stages ----
    for (int s = 0; s < NS; s++) {
        cpa_wait2();          // stage s resident (this thread's groups)
        __syncthreads();      // all threads' stage-s data visible

        const u32 bb = smem_u32(smraw + SM_B + (s % 3) * 32768);
        const int i  = s >> 1;
        const int h  = s & 1;
        const int j2 = s - 256;

        float xv0 = 0.f, xv1 = 0.f;
        if (s < 256) {
            xv0 = XJT[i * 128 + r0b];
            xv1 = XJT[i * 128 + r0b + 8];
        }

        #pragma unroll
        for (int c = 0; c < 4; c++) {     // K16 chunks
            // --- build A fragment (16 unique rows, no duplication) ---
            u32 Ahi[4], Alo[4];
            if (s < 256) {
                const int qb = h * 32 + c * 8 + l4;
                float2 h00 = HT2[qb * HSTR + r0b];
                float2 h01 = HT2[qb * HSTR + r0b + 8];
                float2 h10 = HT2[(qb + 4) * HSTR + r0b];
                float2 h11 = HT2[(qb + 4) * HSTR + r0b + 8];
                split2(xv0 * h00.x, xv0 * h00.y, Ahi[0], Alo[0]);
                split2(xv1 * h01.x, xv1 * h01.y, Ahi[1], Alo[1]);
                split2(xv0 * h10.x, xv0 * h10.y, Ahi[2], Alo[2]);
                split2(xv1 * h11.x, xv1 * h11.y, Ahi[3], Alo[3]);
            } else {
                const int kb = j2 * 64 + c * 16 + l4 * 2;
                split2(XJT[(kb + 0) * 128 + r0b],     XJT[(kb + 1) * 128 + r0b],
                       Ahi[0], Alo[0]);
                split2(XJT[(kb + 0) * 128 + r0b + 8], XJT[(kb + 1) * 128 + r0b + 8],
                       Ahi[1], Alo[1]);
                split2(XJT[(kb + 8) * 128 + r0b],     XJT[(kb + 9) * 128 + r0b],
                       Ahi[2], Alo[2]);
                split2(XJT[(kb + 8) * 128 + r0b + 8], XJT[(kb + 9) * 128 + r0b + 8],
                       Ahi[3], Alo[3]);
            }

            // --- full n range: 8 jj pairs; load B then 6 HMMA per pair ---
            const int grp = lane >> 3;
            const int rr  = lane & 7;
            #pragma unroll
            for (int jj = 0; jj < 8; jj++) {   // n8-block pairs (2jj, 2jj+1)
                const int n = (2 * jj + (grp >> 1)) * 8 + rr;
                const u32 off = (u32)(n * 128 + c * 32 + (grp & 1) * 16);
                const u32 ah = bb + SWZ(off);
                u32 bh0, bh1, bh2, bh3, bl0, bl1, bl2, bl3;
                ldmx4(bh0, bh1, bh2, bh3, ah);
                ldmx4(bl0, bl1, bl2, bl3, ah + 16384);
                u32 Bh0[2] = {bh0, bh1}, Bh1[2] = {bh2, bh3};
                u32 Bl0[2] = {bl0, bl1}, Bl1[2] = {bl2, bl3};
                hmma(dacc[2 * jj],     Ahi, Bh0);
                hmma(dacc[2 * jj],     Ahi, Bl0);
                hmma(dacc[2 * jj],     Alo, Bh0);
                hmma(dacc[2 * jj + 1], Ahi, Bh1);
                hmma(dacc[2 * jj + 1], Ahi, Bl1);
                hmma(dacc[2 * jj + 1], Alo, Bh1);
            }
        }
        __syncthreads();      // all reads of buf s%3 done before refill below

        // issue stage s+3 into buf (s+3)%3 == s%3
        const int sp = s + 3;
        if (sp < NS) {
            u32 db = smem_u32(smraw + SM_B + (sp % 3) * 32768) + tid * 16;
            const unsigned char* sh = g_Bhi + (size_t)sp * IMG + tid * 16;
            const unsigned char* sl = g_Blo + (size_t)sp * IMG + tid * 16;
            #pragma unroll
            for (int r = 0; r < 4; r++) {
                cpa16(db + r * 4096,         sh + r * 4096);
                cpa16(db + 16384 + r * 4096, sl + r * 4096);
            }
        }
        cpa_commit();
    }

    // ---- epilogue: scatter-add fragments into g_seg ----
    {
        const int d0i = load_edge(ei, 1, e0 + r0b,     is64);
        const int d1i = load_edge(ei, 1, e0 + r0b + 8, is64);
        float* g0 = g_seg + (size_t)d0i * D;
        float* g1 = g_seg + (size_t)d1i * D;
        #pragma unroll
        for (int j = 0; j < 16; j++) {
            const int nc = j * 8 + l4 * 2;
            atomicAdd(&g0[nc],     dacc[j][0]);
            atomicAdd(&g0[nc + 1], dacc[j][1]);
            atomicAdd(&g1[nc],     dacc[j][2]);
            atomicAdd(&g1[nc + 1], dacc[j][3]);
        }
    }
}

// ---------------- node kernel: out = x + gelu(aggr + x@root + bias) ----------------
#define NSTR 132
#define NODE_SMEM_BYTES ((128 * NSTR + 128 * 128) * 4)

__global__ __launch_bounds__(256, 1) void node_kernel(
    const float* __restrict__ x, const float* __restrict__ root,
    const float* __restrict__ bias, float* __restrict__ out)
{
    extern __shared__ float sm[];
    float* XT = sm;
    float* Rs = sm + 128 * NSTR;

    const int tid = threadIdx.x;
    const int tx  = tid & 15;
    const int ty  = tid >> 4;
    const int n0  = blockIdx.x * 128;

    {
        const int e  = tid >> 1;
        const int c0 = (tid & 1) * 64;
        const int n  = n0 + e;
        if (n < NN) {
            const float* row = x + (size_t)n * D + c0;
            #pragma unroll
            for (int j = 0; j < 64; j += 4) {
                float4 v = *(const float4*)(row + j);
                XT[(c0 + j + 0) * NSTR + e] = v.x;
                XT[(c0 + j + 1) * NSTR + e] = v.y;
                XT[(c0 + j + 2) * NSTR + e] = v.z;
                XT[(c0 + j + 3) * NSTR + e] = v.w;
            }
        } else {
            #pragma unroll
            for (int j = 0; j < 64; j++)
                XT[(c0 + j) * NSTR + e] = 0.f;
        }
        const float* rr = root + (size_t)(tid >> 1) * D + c0;
        float* rd = Rs + (tid >> 1) * 128 + c0;
        #pragma unroll
        for (int j = 0; j < 64; j += 4)
            *(float4*)(rd + j) = *(const float4*)(rr + j);
    }
    __syncthreads();

    float acc[8][8];
    #pragma unroll
    for (int r = 0; r < 8; r++)
        #pragma unroll
        for (int c = 0; c < 8; c++) acc[r][c] = 0.f;

    for (int c = 0; c < 128; c++) {
        float4 aL = *(const float4*)&XT[c * NSTR + ty * 8];
        float4 aH = *(const float4*)&XT[c * NSTR + ty * 8 + 4];
        float4 bL = *(const float4*)&Rs[c * 128 + tx * 8];
        float4 bH = *(const float4*)&Rs[c * 128 + tx * 8 + 4];
        float a[8] = {aL.x, aL.y, aL.z, aL.w, aH.x, aH.y, aH.z, aH.w};
        float b[8] = {bL.x, bL.y, bL.z, bL.w, bH.x, bH.y, bH.z, bH.w};
        #pragma unroll
        for (int r = 0; r < 8; r++)
            #pragma unroll
            for (int c2 = 0; c2 < 8; c2++)
                acc[r][c2] = fmaf(a[r], b[c2], acc[r][c2]);
    }

    #pragma unroll
    for (int r = 0; r < 8; r++) {
        const int n = n0 + ty * 8 + r;
        if (n >= NN) continue;
        const float invc = 1.f / fmaxf(g_cnt[n], 1.f);
        #pragma unroll
        for (int c = 0; c < 8; c++) {
            const int o = tx * 8 + c;
            float cv = acc[r][c] + bias[o] + g_seg[(size_t)n * D + o] * invc;
            float xv = XT[o * NSTR + ty * 8 + r];
            out[(size_t)n * D + o] = xv + cv * normcdff(cv);
        }
    }
}

// ---------------- launch ----------------
extern "C" void kernel_launch(void* const* d_in, const int* in_sizes, int n_in,
                              void* d_out, int out_size)
{
    const float* x    = (const float*)d_in[0];
    const int*   ei   = (const int*)  d_in[1];
    const float* ea   = (const float*)d_in[2];
    const float* w1   = (const float*)d_in[3];
    const float* b1   = (const float*)d_in[4];
    const float* w2   = (const float*)d_in[5];
    const float* b2   = (const float*)d_in[6];
    const float* root = (const float*)d_in[7];
    const float* bias = (const float*)d_in[8];
    float* out = (float*)d_out;

    cudaFuncSetAttribute(edge_kernel, cudaFuncAttributeMaxDynamicSharedMemorySize,
                         EDGE_SMEM_BYTES);
    cudaFuncSetAttribute(node_kernel, cudaFuncAttributeMaxDynamicSharedMemorySize,
                         NODE_SMEM_BYTES);

    detect_kernel<<<1, 32>>>(ei);
    zero_kernel<<<(NN * D + 255) / 256, 256>>>();
    cnt_kernel<<<(NE + 255) / 256, 256>>>(ei);
    prep_kernel<<<NS, 128>>>(w2, b2);
    edge_kernel<<<NE / 128, 256, EDGE_SMEM_BYTES>>>(x, ei, ea, w1, b1);
    node_kernel<<<(NN + 127) / 128, 256, NODE_SMEM_BYTES>>>(x, root, bias, out);
}